// round 1
// baseline (speedup 1.0000x reference)
#include <cuda_runtime.h>
#include <math.h>

#define B   10
#define V   50257
#define D   1024
#define T   20
#define NCHUNK 13
#define CHUNK  4096   // 13*4096 = 53248 >= V

// ------------------------- device scratch (no allocs allowed) -------------
__device__ float g_logits[B * V];
__device__ float g_pm[B * NCHUNK];
__device__ float g_ps[B * NCHUNK];
__device__ float g_pv[B * NCHUNK * B];
__device__ int   g_pi[B * NCHUNK * B];
__device__ int   g_tokens[B];
__device__ int   g_q[B];
__device__ int   g_seq[2][T * B];
__device__ float g_lp[2][T * B];
__device__ float g_bsum[2][B];
__device__ float g_h[2][B * D];
__device__ float g_rpart[8][B * D];

// --------------------------- helpers ---------------------------------------
__device__ __forceinline__ unsigned long long fma2(unsigned long long a,
                                                   unsigned long long b,
                                                   unsigned long long c) {
    unsigned long long d;
    asm("fma.rn.f32x2 %0, %1, %2, %3;" : "=l"(d) : "l"(a), "l"(b), "l"(c));
    return d;
}
__device__ __forceinline__ unsigned long long pack2(float w) {
    unsigned int wu = __float_as_uint(w);
    unsigned long long r;
    asm("mov.b64 %0, {%1, %1};" : "=l"(r) : "r"(wu));
    return r;
}
__device__ __forceinline__ void unpack2(unsigned long long a, float& lo, float& hi) {
    unsigned int l, h;
    asm("mov.b64 {%0, %1}, %2;" : "=r"(l), "=r"(h) : "l"(a));
    lo = __uint_as_float(l); hi = __uint_as_float(h);
}

// --------------------------- init ------------------------------------------
__global__ void init_kernel(const float* __restrict__ h0) {
    int i = blockIdx.x * 256 + threadIdx.x;
    if (i < B * D) g_h[0][i] = h0[i];
    if (i < T * B) { g_seq[0][i] = 0; g_seq[1][i] = 0; g_lp[0][i] = 0.f; g_lp[1][i] = 0.f; }
    if (i < B)     { g_bsum[0][i] = 0.f; g_bsum[1][i] = 0.f; }
}

// --------------------------- top-k partial ----------------------------------
// grid (NCHUNK, B), 256 threads. Per-thread sorted top-10 + online logsumexp,
// then block tournament reduce (per-thread lists, pop winner's head).
__global__ void topk_partial_kernel(const float* __restrict__ src, int use_input) {
    const int beam = blockIdx.y, chunk = blockIdx.x, tid = threadIdx.x;
    const float* row = (use_input ? src : (const float*)g_logits) + beam * V;
    const int c0 = chunk * CHUNK;
    const int c1 = min(c0 + CHUNK, V);

    float m = -1e30f, s = 0.f;
    float tv[10]; int ti[10];
#pragma unroll
    for (int p = 0; p < 10; p++) { tv[p] = -1e30f; ti[p] = 0x7FFFFFFF; }

    for (int c = c0 + tid; c < c1; c += 256) {
        float x = row[c];
        if (x > m) { s = s * __expf(m - x) + 1.f; m = x; }
        else       { s += __expf(x - m); }
        float v = (c == V - 1) ? x - 1000.f : x;    // UNK suppression (top-k only)
        if (v > tv[9] || (v == tv[9] && c < ti[9])) {
            tv[9] = v; ti[9] = c;
#pragma unroll
            for (int p = 9; p > 0; p--) {
                bool sw = (tv[p] > tv[p-1]) || (tv[p] == tv[p-1] && ti[p] < ti[p-1]);
                if (sw) {
                    float tf = tv[p]; tv[p] = tv[p-1]; tv[p-1] = tf;
                    int   tt = ti[p]; ti[p] = ti[p-1]; ti[p-1] = tt;
                }
            }
        }
    }

    // block logsumexp reduce
    __shared__ float sm[256], ss[256];
    sm[tid] = m; ss[tid] = s; __syncthreads();
    for (int off = 128; off > 0; off >>= 1) {
        if (tid < off) {
            float m1 = sm[tid], s1 = ss[tid], m2 = sm[tid + off], s2 = ss[tid + off];
            float mm = fmaxf(m1, m2);
            sm[tid] = mm;
            ss[tid] = s1 * __expf(m1 - mm) + s2 * __expf(m2 - mm);
        }
        __syncthreads();
    }
    if (tid == 0) { g_pm[beam * NCHUNK + chunk] = sm[0]; g_ps[beam * NCHUNK + chunk] = ss[0]; }

    // block top-10 tournament over 256 sorted per-thread lists
    __shared__ float rv[256]; __shared__ int rc[256]; __shared__ int rt[256];
    for (int r = 0; r < 10; r++) {
        rv[tid] = tv[0]; rc[tid] = ti[0]; rt[tid] = tid;
        __syncthreads();
        for (int off = 128; off > 0; off >>= 1) {
            if (tid < off) {
                bool take = (rv[tid+off] > rv[tid]) ||
                            (rv[tid+off] == rv[tid] && rc[tid+off] < rc[tid]);
                if (take) { rv[tid] = rv[tid+off]; rc[tid] = rc[tid+off]; rt[tid] = rt[tid+off]; }
            }
            __syncthreads();
        }
        if (tid == 0) {
            int slot = (beam * NCHUNK + chunk) * 10 + r;
            g_pv[slot] = rv[0]; g_pi[slot] = rc[0];
        }
        int wint = rt[0];
        __syncthreads();
        if (tid == wint) {
#pragma unroll
            for (int p = 0; p < 9; p++) { tv[p] = tv[p+1]; ti[p] = ti[p+1]; }
            tv[9] = -1e30f; ti[9] = 0x7FFFFFFF;
        }
    }
}

// --------------------------- reduce + select --------------------------------
// 1 block x 320 threads. Warp w<10 merges beam w's 13 partial lists + lse via
// shuffles; then warp 0 does the global 100->10 selection; then bookkeeping.
__global__ void reduce_select_kernel(int t, int cur) {
    __shared__ float s_topv[100];
    __shared__ int   s_topi[100];
    __shared__ int   s_q[10], s_tok[10];
    __shared__ float s_loc[10], s_ns[10];
    const unsigned FULL = 0xffffffffu;
    int tid = threadIdx.x, w = tid >> 5, lane = tid & 31;
    int nxt = cur ^ 1;

    if (w < 10) {
        int beam = w;
        // logsumexp across chunks
        float m = -1e30f, s = 0.f;
        if (lane < NCHUNK) { m = g_pm[beam * NCHUNK + lane]; s = g_ps[beam * NCHUNK + lane]; }
#pragma unroll
        for (int off = 16; off > 0; off >>= 1) {
            float m2 = __shfl_down_sync(FULL, m, off);
            float s2 = __shfl_down_sync(FULL, s, off);
            float mm = fmaxf(m, m2);
            s = s * __expf(m - mm) + s2 * __expf(m2 - mm);
            m = mm;
        }
        float mf = __shfl_sync(FULL, m, 0);
        float sf = __shfl_sync(FULL, s, 0);
        float lse = logf(sf) + mf;

        // lane l owns sorted partial list l (preloaded into registers)
        float lv[10]; int li[10];
        if (lane < NCHUNK) {
            int base = (beam * NCHUNK + lane) * 10;
#pragma unroll
            for (int p = 0; p < 10; p++) { lv[p] = g_pv[base + p]; li[p] = g_pi[base + p]; }
        } else {
#pragma unroll
            for (int p = 0; p < 10; p++) { lv[p] = -1e30f; li[p] = 0x7FFFFFFF; }
        }
        for (int r = 0; r < 10; r++) {
            float v = lv[0]; int c = li[0]; int l = lane;
#pragma unroll
            for (int off = 16; off > 0; off >>= 1) {
                float v2 = __shfl_down_sync(FULL, v, off);
                int   c2 = __shfl_down_sync(FULL, c, off);
                int   l2 = __shfl_down_sync(FULL, l, off);
                if (v2 > v || (v2 == v && c2 < c)) { v = v2; c = c2; l = l2; }
            }
            v = __shfl_sync(FULL, v, 0); c = __shfl_sync(FULL, c, 0); l = __shfl_sync(FULL, l, 0);
            if (lane == 0) { s_topv[beam * 10 + r] = v - lse; s_topi[beam * 10 + r] = c; }
            if (lane == l) {
#pragma unroll
                for (int p = 0; p < 9; p++) { lv[p] = lv[p+1]; li[p] = li[p+1]; }
                lv[9] = -1e30f; li[9] = 0x7FFFFFFF;
            }
        }
    }
    __syncthreads();

    if (w == 0) {
        float cv[4]; int cf[4];
#pragma unroll
        for (int j = 0; j < 4; j++) {
            int f = lane + 32 * j;
            if (f < 100) {
                int i = f / 10;
                float val = g_bsum[cur][i] + s_topv[f];
                if (t == 0 && i > 0) val = -1e10f;
                cv[j] = val; cf[j] = f;
            } else { cv[j] = -1e30f; cf[j] = 0x7FFFFFFF; }
        }
        for (int r = 0; r < 10; r++) {
            float bv = -1e30f; int bf = 0x7FFFFFFF;
#pragma unroll
            for (int j = 0; j < 4; j++)
                if (cv[j] > bv || (cv[j] == bv && cf[j] < bf)) { bv = cv[j]; bf = cf[j]; }
#pragma unroll
            for (int off = 16; off > 0; off >>= 1) {
                float v2 = __shfl_down_sync(FULL, bv, off);
                int   f2 = __shfl_down_sync(FULL, bf, off);
                if (v2 > bv || (v2 == bv && f2 < bf)) { bv = v2; bf = f2; }
            }
            bv = __shfl_sync(FULL, bv, 0); bf = __shfl_sync(FULL, bf, 0);
            if (lane == 0) {
                int qq = bf / 10;
                s_q[r] = qq; s_tok[r] = s_topi[bf]; s_loc[r] = s_topv[bf]; s_ns[r] = bv;
            }
#pragma unroll
            for (int j = 0; j < 4; j++) if (cf[j] == bf) cv[j] = -1e30f;
        }
    }
    __syncthreads();

    if (tid < 10) {
        g_tokens[tid] = s_tok[tid];
        g_q[tid]      = s_q[tid];
        g_bsum[nxt][tid] = (s_tok[tid] == 0) ? -1000.0f : s_ns[tid];
    }
    for (int i = tid; i < T * B; i += 320) {
        int b = i % 10, row = i / 10;
        int sb = s_q[b];
        int sv; float lv2;
        if (row == t) { sv = s_tok[b]; lv2 = s_loc[b]; }
        else          { sv = g_seq[cur][row * 10 + sb]; lv2 = g_lp[cur][row * 10 + sb]; }
        g_seq[nxt][i] = sv; g_lp[nxt][i] = lv2;
    }
}

// --------------------------- RNN (split-K partials) ------------------------
// grid 64 = 8 col-blocks x 8 k-slices, 128 threads. Reads wx/wh exactly once.
__global__ void rnn_partial_kernel(const float* __restrict__ emb,
                                   const float* __restrict__ wx,
                                   const float* __restrict__ wh, int cur) {
    __shared__ float se[128 * 12], shh[128 * 12];
    __shared__ int stok[10], sq[10];
    int bx = blockIdx.x;
    int cb = bx & 7, ks = bx >> 3;
    int tid = threadIdx.x;
    int k0 = ks * 128;

    if (tid < 10) { stok[tid] = g_tokens[tid]; sq[tid] = g_q[tid]; }
    __syncthreads();

    for (int i = tid; i < 1280; i += 128) {
        int b = i >> 7, kk = i & 127;
        se[kk * 12 + b]  = emb[(size_t)stok[b] * D + k0 + kk];
        shh[kk * 12 + b] = g_h[cur][sq[b] * D + k0 + kk];
    }
    __syncthreads();

    int col = cb * 128 + tid;
    float acc[10];
#pragma unroll
    for (int b = 0; b < 10; b++) acc[b] = 0.f;
#pragma unroll 4
    for (int kk = 0; kk < 128; kk++) {
        float wxv = __ldg(&wx[(k0 + kk) * D + col]);
        float whv = __ldg(&wh[(k0 + kk) * D + col]);
#pragma unroll
        for (int b = 0; b < 10; b++)
            acc[b] += se[kk * 12 + b] * wxv + shh[kk * 12 + b] * whv;
    }
#pragma unroll
    for (int b = 0; b < 10; b++) g_rpart[ks][b * D + col] = acc[b];
}

__global__ void rnn_combine_kernel(int nxt) {
    int i = blockIdx.x * 256 + threadIdx.x;
    if (i < B * D) {
        float v = 0.f;
#pragma unroll
        for (int ks = 0; ks < 8; ks++) v += g_rpart[ks][i];
        g_h[nxt][i] = tanhf(v);
    }
}

// --------------------------- logits = h @ wo (f32x2 packed) ----------------
// grid 148 x 256. Each block: load all 10 h rows into shared (packed f32x2
// beam-pairs), then 340 contiguous columns; thread does full-K dot with 5
// packed accumulators (10 beams). wo read exactly once per step.
#define COLS_PER_BLK 340
__global__ void logits_kernel(const float* __restrict__ wo, int hbuf) {
    __shared__ unsigned long long hs2[D * 6];   // [k][beam-pair], stride 48B
    float* hsf = (float*)hs2;
    const float* h = g_h[hbuf];
    for (int i = threadIdx.x; i < B * D; i += 256) {
        int b = i >> 10, k = i & 1023;
        hsf[k * 12 + b] = h[i];
    }
    __syncthreads();

    int base = blockIdx.x * COLS_PER_BLK;
    for (int cc = threadIdx.x; cc < COLS_PER_BLK; cc += 256) {
        int c = base + cc;
        if (c >= V) break;
        const float* wcol = wo + c;
        unsigned long long a0 = 0, a1 = 0, a2 = 0, a3 = 0, a4 = 0;
#pragma unroll 4
        for (int k = 0; k < D; k++) {
            float wv = __ldg(wcol + k * V);
            unsigned long long w2 = pack2(wv);
            const unsigned long long* hp = &hs2[k * 6];
            a0 = fma2(hp[0], w2, a0);
            a1 = fma2(hp[1], w2, a1);
            a2 = fma2(hp[2], w2, a2);
            a3 = fma2(hp[3], w2, a3);
            a4 = fma2(hp[4], w2, a4);
        }
        float lo, hi;
        unpack2(a0, lo, hi); g_logits[0 * V + c] = lo; g_logits[1 * V + c] = hi;
        unpack2(a1, lo, hi); g_logits[2 * V + c] = lo; g_logits[3 * V + c] = hi;
        unpack2(a2, lo, hi); g_logits[4 * V + c] = lo; g_logits[5 * V + c] = hi;
        unpack2(a3, lo, hi); g_logits[6 * V + c] = lo; g_logits[7 * V + c] = hi;
        unpack2(a4, lo, hi); g_logits[8 * V + c] = lo; g_logits[9 * V + c] = hi;
    }
}

// --------------------------- finalize ---------------------------------------
__global__ void finalize_kernel(float* __restrict__ out, int cur) {
    int i = blockIdx.x * 256 + threadIdx.x;
    if (i < T * B)               out[i] = (float)g_seq[cur][i];
    else if (i < 2 * T * B)      out[i] = g_lp[cur][i - T * B];
    else if (i < 2 * T * B + B)  out[i] = g_bsum[cur][i - 2 * T * B];
}

// --------------------------- host driver ------------------------------------
extern "C" void kernel_launch(void* const* d_in, const int* in_sizes, int n_in,
                              void* d_out, int out_size) {
    const float* logprobs0 = (const float*)d_in[0];
    const float* h0        = (const float*)d_in[1];
    const float* emb       = (const float*)d_in[2];
    const float* wx        = (const float*)d_in[3];
    const float* wh        = (const float*)d_in[4];
    const float* wo        = (const float*)d_in[5];
    float* out = (float*)d_out;

    init_kernel<<<48, 256>>>(h0);

    int cur = 0;
    for (int t = 0; t < T; t++) {
        dim3 gtp(NCHUNK, B);
        topk_partial_kernel<<<gtp, 256>>>(logprobs0, t == 0 ? 1 : 0);
        reduce_select_kernel<<<1, 320>>>(t, cur);
        if (t < T - 1) {
            rnn_partial_kernel<<<64, 128>>>(emb, wx, wh, cur);
            rnn_combine_kernel<<<40, 256>>>(cur ^ 1);
            logits_kernel<<<148, 256>>>(wo, cur ^ 1);
        }
        cur ^= 1;
    }
    finalize_kernel<<<2, 256>>>(out, cur);
}

// round 2
// speedup vs baseline: 2.5924x; 2.5924x over previous
#include <cuda_runtime.h>
#include <math.h>

#define B   10
#define V   50257
#define D   1024
#define T   20
#define NCHUNK 13
#define CHUNK  4096   // 13*4096 = 53248 >= V

#define RNN_KS 32     // k-slices of 32
#define RNN_CB 4      // col blocks of 256

// ------------------------- device scratch (no allocs allowed) -------------
__device__ float g_logits[B * V];
__device__ float g_pm[B * NCHUNK];
__device__ float g_ps[B * NCHUNK];
__device__ float g_pv[B * NCHUNK * B];
__device__ int   g_pi[B * NCHUNK * B];
__device__ int   g_tokens[B];
__device__ int   g_q[B];
__device__ int   g_seq[2][T * B];
__device__ float g_lp[2][T * B];
__device__ float g_bsum[2][B];
__device__ float g_h[2][B * D];
__device__ float g_rpart[RNN_KS][B * D];

// --------------------------- helpers ---------------------------------------
__device__ __forceinline__ unsigned long long fma2(unsigned long long a,
                                                   unsigned long long b,
                                                   unsigned long long c) {
    unsigned long long d;
    asm("fma.rn.f32x2 %0, %1, %2, %3;" : "=l"(d) : "l"(a), "l"(b), "l"(c));
    return d;
}
__device__ __forceinline__ unsigned long long pack2(float w) {
    unsigned int wu = __float_as_uint(w);
    unsigned long long r;
    asm("mov.b64 %0, {%1, %1};" : "=l"(r) : "r"(wu));
    return r;
}
__device__ __forceinline__ void unpack2(unsigned long long a, float& lo, float& hi) {
    unsigned int l, h;
    asm("mov.b64 {%0, %1}, %2;" : "=r"(l), "=r"(h) : "l"(a));
    lo = __uint_as_float(l); hi = __uint_as_float(h);
}

// --------------------------- init ------------------------------------------
__global__ void init_kernel(const float* __restrict__ h0) {
    int i = blockIdx.x * 256 + threadIdx.x;
    if (i < B * D) g_h[0][i] = h0[i];
    if (i < T * B) { g_seq[0][i] = 0; g_seq[1][i] = 0; g_lp[0][i] = 0.f; g_lp[1][i] = 0.f; }
    if (i < B)     { g_bsum[0][i] = 0.f; g_bsum[1][i] = 0.f; }
}

// --------------------------- top-k partial ----------------------------------
// grid (NCHUNK, B), 256 threads. Per-thread sorted top-10 + online logsumexp,
// then block tournament reduce (per-thread lists, pop winner's head).
__global__ void topk_partial_kernel(const float* __restrict__ src, int use_input) {
    const int beam = blockIdx.y, chunk = blockIdx.x, tid = threadIdx.x;
    const float* row = (use_input ? src : (const float*)g_logits) + beam * V;
    const int c0 = chunk * CHUNK;
    const int c1 = min(c0 + CHUNK, V);

    float m = -1e30f, s = 0.f;
    float tv[10]; int ti[10];
#pragma unroll
    for (int p = 0; p < 10; p++) { tv[p] = -1e30f; ti[p] = 0x7FFFFFFF; }

    for (int c = c0 + tid; c < c1; c += 256) {
        float x = row[c];
        if (x > m) { s = s * __expf(m - x) + 1.f; m = x; }
        else       { s += __expf(x - m); }
        float v = (c == V - 1) ? x - 1000.f : x;    // UNK suppression (top-k only)
        if (v > tv[9] || (v == tv[9] && c < ti[9])) {
            tv[9] = v; ti[9] = c;
#pragma unroll
            for (int p = 9; p > 0; p--) {
                bool sw = (tv[p] > tv[p-1]) || (tv[p] == tv[p-1] && ti[p] < ti[p-1]);
                if (sw) {
                    float tf = tv[p]; tv[p] = tv[p-1]; tv[p-1] = tf;
                    int   tt = ti[p]; ti[p] = ti[p-1]; ti[p-1] = tt;
                }
            }
        }
    }

    // block logsumexp reduce
    __shared__ float sm[256], ss[256];
    sm[tid] = m; ss[tid] = s; __syncthreads();
    for (int off = 128; off > 0; off >>= 1) {
        if (tid < off) {
            float m1 = sm[tid], s1 = ss[tid], m2 = sm[tid + off], s2 = ss[tid + off];
            float mm = fmaxf(m1, m2);
            sm[tid] = mm;
            ss[tid] = s1 * __expf(m1 - mm) + s2 * __expf(m2 - mm);
        }
        __syncthreads();
    }
    if (tid == 0) { g_pm[beam * NCHUNK + chunk] = sm[0]; g_ps[beam * NCHUNK + chunk] = ss[0]; }

    // block top-10 tournament over 256 sorted per-thread lists
    __shared__ float rv[256]; __shared__ int rc[256]; __shared__ int rt[256];
    for (int r = 0; r < 10; r++) {
        rv[tid] = tv[0]; rc[tid] = ti[0]; rt[tid] = tid;
        __syncthreads();
        for (int off = 128; off > 0; off >>= 1) {
            if (tid < off) {
                bool take = (rv[tid+off] > rv[tid]) ||
                            (rv[tid+off] == rv[tid] && rc[tid+off] < rc[tid]);
                if (take) { rv[tid] = rv[tid+off]; rc[tid] = rc[tid+off]; rt[tid] = rt[tid+off]; }
            }
            __syncthreads();
        }
        if (tid == 0) {
            int slot = (beam * NCHUNK + chunk) * 10 + r;
            g_pv[slot] = rv[0]; g_pi[slot] = rc[0];
        }
        int wint = rt[0];
        __syncthreads();
        if (tid == wint) {
#pragma unroll
            for (int p = 0; p < 9; p++) { tv[p] = tv[p+1]; ti[p] = ti[p+1]; }
            tv[9] = -1e30f; ti[9] = 0x7FFFFFFF;
        }
    }
}

// --------------------------- reduce + select --------------------------------
// 1 block x 320 threads. Warp w<10 merges beam w's 13 partial lists + lse via
// shuffles; then warp 0 does the global 100->10 selection; then bookkeeping.
__global__ void reduce_select_kernel(int t, int cur) {
    __shared__ float s_topv[100];
    __shared__ int   s_topi[100];
    __shared__ int   s_q[10], s_tok[10];
    __shared__ float s_loc[10], s_ns[10];
    const unsigned FULL = 0xffffffffu;
    int tid = threadIdx.x, w = tid >> 5, lane = tid & 31;
    int nxt = cur ^ 1;

    if (w < 10) {
        int beam = w;
        // logsumexp across chunks
        float m = -1e30f, s = 0.f;
        if (lane < NCHUNK) { m = g_pm[beam * NCHUNK + lane]; s = g_ps[beam * NCHUNK + lane]; }
#pragma unroll
        for (int off = 16; off > 0; off >>= 1) {
            float m2 = __shfl_down_sync(FULL, m, off);
            float s2 = __shfl_down_sync(FULL, s, off);
            float mm = fmaxf(m, m2);
            s = s * __expf(m - mm) + s2 * __expf(m2 - mm);
            m = mm;
        }
        float mf = __shfl_sync(FULL, m, 0);
        float sf = __shfl_sync(FULL, s, 0);
        float lse = logf(sf) + mf;

        // lane l owns sorted partial list l (preloaded into registers)
        float lv[10]; int li[10];
        if (lane < NCHUNK) {
            int base = (beam * NCHUNK + lane) * 10;
#pragma unroll
            for (int p = 0; p < 10; p++) { lv[p] = g_pv[base + p]; li[p] = g_pi[base + p]; }
        } else {
#pragma unroll
            for (int p = 0; p < 10; p++) { lv[p] = -1e30f; li[p] = 0x7FFFFFFF; }
        }
        for (int r = 0; r < 10; r++) {
            float v = lv[0]; int c = li[0]; int l = lane;
#pragma unroll
            for (int off = 16; off > 0; off >>= 1) {
                float v2 = __shfl_down_sync(FULL, v, off);
                int   c2 = __shfl_down_sync(FULL, c, off);
                int   l2 = __shfl_down_sync(FULL, l, off);
                if (v2 > v || (v2 == v && c2 < c)) { v = v2; c = c2; l = l2; }
            }
            v = __shfl_sync(FULL, v, 0); c = __shfl_sync(FULL, c, 0); l = __shfl_sync(FULL, l, 0);
            if (lane == 0) { s_topv[beam * 10 + r] = v - lse; s_topi[beam * 10 + r] = c; }
            if (lane == l) {
#pragma unroll
                for (int p = 0; p < 9; p++) { lv[p] = lv[p+1]; li[p] = li[p+1]; }
                lv[9] = -1e30f; li[9] = 0x7FFFFFFF;
            }
        }
    }
    __syncthreads();

    if (w == 0) {
        float cv[4]; int cf[4];
#pragma unroll
        for (int j = 0; j < 4; j++) {
            int f = lane + 32 * j;
            if (f < 100) {
                int i = f / 10;
                float val = g_bsum[cur][i] + s_topv[f];
                if (t == 0 && i > 0) val = -1e10f;
                cv[j] = val; cf[j] = f;
            } else { cv[j] = -1e30f; cf[j] = 0x7FFFFFFF; }
        }
        for (int r = 0; r < 10; r++) {
            float bv = -1e30f; int bf = 0x7FFFFFFF;
#pragma unroll
            for (int j = 0; j < 4; j++)
                if (cv[j] > bv || (cv[j] == bv && cf[j] < bf)) { bv = cv[j]; bf = cf[j]; }
#pragma unroll
            for (int off = 16; off > 0; off >>= 1) {
                float v2 = __shfl_down_sync(FULL, bv, off);
                int   f2 = __shfl_down_sync(FULL, bf, off);
                if (v2 > bv || (v2 == bv && f2 < bf)) { bv = v2; bf = f2; }
            }
            bv = __shfl_sync(FULL, bv, 0); bf = __shfl_sync(FULL, bf, 0);
            if (lane == 0) {
                int qq = bf / 10;
                s_q[r] = qq; s_tok[r] = s_topi[bf]; s_loc[r] = s_topv[bf]; s_ns[r] = bv;
            }
#pragma unroll
            for (int j = 0; j < 4; j++) if (cf[j] == bf) cv[j] = -1e30f;
        }
    }
    __syncthreads();

    if (tid < 10) {
        g_tokens[tid] = s_tok[tid];
        g_q[tid]      = s_q[tid];
        g_bsum[nxt][tid] = (s_tok[tid] == 0) ? -1000.0f : s_ns[tid];
    }
    for (int i = tid; i < T * B; i += 320) {
        int b = i % 10, row = i / 10;
        int sb = s_q[b];
        int sv; float lv2;
        if (row == t) { sv = s_tok[b]; lv2 = s_loc[b]; }
        else          { sv = g_seq[cur][row * 10 + sb]; lv2 = g_lp[cur][row * 10 + sb]; }
        g_seq[nxt][i] = sv; g_lp[nxt][i] = lv2;
    }
}

// --------------------------- RNN (split-K partials) ------------------------
// grid 128 = 4 col-blocks(256 cols) x 32 k-slices(32 k), 256 threads.
// Reads wx/wh exactly once with ~2MB in flight chip-wide.
__global__ __launch_bounds__(256) void rnn_partial_kernel(
        const float* __restrict__ emb,
        const float* __restrict__ wx,
        const float* __restrict__ wh, int cur) {
    __shared__ float se[32 * 12], shh[32 * 12];
    __shared__ int stok[10], sq[10];
    int bx = blockIdx.x;
    int cb = bx & 3, ks = bx >> 2;
    int tid = threadIdx.x;
    int k0 = ks * 32;

    if (tid < 10) { stok[tid] = g_tokens[tid]; sq[tid] = g_q[tid]; }
    __syncthreads();

    for (int i = tid; i < 320; i += 256) {
        int b = i >> 5, kk = i & 31;
        se[kk * 12 + b]  = emb[(size_t)stok[b] * D + k0 + kk];
        shh[kk * 12 + b] = g_h[cur][sq[b] * D + k0 + kk];
    }
    __syncthreads();

    int col = cb * 256 + tid;
    float acc[10];
#pragma unroll
    for (int b = 0; b < 10; b++) acc[b] = 0.f;
#pragma unroll 8
    for (int kk = 0; kk < 32; kk++) {
        float wxv = __ldg(&wx[(size_t)(k0 + kk) * D + col]);
        float whv = __ldg(&wh[(size_t)(k0 + kk) * D + col]);
#pragma unroll
        for (int b = 0; b < 10; b++)
            acc[b] += se[kk * 12 + b] * wxv + shh[kk * 12 + b] * whv;
    }
#pragma unroll
    for (int b = 0; b < 10; b++) g_rpart[ks][b * D + col] = acc[b];
}

__global__ void rnn_combine_kernel(int nxt) {
    int i = blockIdx.x * 256 + threadIdx.x;
    if (i < B * D) {
        float v = 0.f;
#pragma unroll
        for (int ks = 0; ks < RNN_KS; ks++) v += g_rpart[ks][i];
        g_h[nxt][i] = tanhf(v);
    }
}

// --------------------------- logits = h @ wo (f32x2 packed) ----------------
// grid 99 x 512. One column per thread, K in chunks of 16 with all loads
// batched up front (MLP=16 -> ~3.2MB in flight chip-wide, DRAM-bound).
#define LOG_BLOCKS 99
#define LOG_THREADS 512
__global__ __launch_bounds__(LOG_THREADS) void logits_kernel(
        const float* __restrict__ wo, int hbuf) {
    __shared__ unsigned long long hs2[D * 6];   // [k][beam-pair], 48KB
    float* hsf = (float*)hs2;
    const float* h = g_h[hbuf];
    for (int i = threadIdx.x; i < B * D; i += LOG_THREADS) {
        int b = i >> 10, k = i & 1023;
        hsf[k * 12 + b] = h[i];
    }
    __syncthreads();

    int c = blockIdx.x * LOG_THREADS + threadIdx.x;
    if (c >= V) return;
    const float* wcol = wo + c;

    unsigned long long a0 = 0, a1 = 0, a2 = 0, a3 = 0, a4 = 0;
    for (int k0 = 0; k0 < D; k0 += 16) {
        float w[16];
#pragma unroll
        for (int i = 0; i < 16; i++)
            w[i] = __ldg(wcol + (size_t)(k0 + i) * V);
#pragma unroll
        for (int i = 0; i < 16; i++) {
            unsigned long long w2 = pack2(w[i]);
            const unsigned long long* hp = &hs2[(k0 + i) * 6];
            a0 = fma2(hp[0], w2, a0);
            a1 = fma2(hp[1], w2, a1);
            a2 = fma2(hp[2], w2, a2);
            a3 = fma2(hp[3], w2, a3);
            a4 = fma2(hp[4], w2, a4);
        }
    }
    float lo, hi;
    unpack2(a0, lo, hi); g_logits[0 * V + c] = lo; g_logits[1 * V + c] = hi;
    unpack2(a1, lo, hi); g_logits[2 * V + c] = lo; g_logits[3 * V + c] = hi;
    unpack2(a2, lo, hi); g_logits[4 * V + c] = lo; g_logits[5 * V + c] = hi;
    unpack2(a3, lo, hi); g_logits[6 * V + c] = lo; g_logits[7 * V + c] = hi;
    unpack2(a4, lo, hi); g_logits[8 * V + c] = lo; g_logits[9 * V + c] = hi;
}

// --------------------------- finalize ---------------------------------------
__global__ void finalize_kernel(float* __restrict__ out, int cur) {
    int i = blockIdx.x * 256 + threadIdx.x;
    if (i < T * B)               out[i] = (float)g_seq[cur][i];
    else if (i < 2 * T * B)      out[i] = g_lp[cur][i - T * B];
    else if (i < 2 * T * B + B)  out[i] = g_bsum[cur][i - 2 * T * B];
}

// --------------------------- host driver ------------------------------------
extern "C" void kernel_launch(void* const* d_in, const int* in_sizes, int n_in,
                              void* d_out, int out_size) {
    const float* logprobs0 = (const float*)d_in[0];
    const float* h0        = (const float*)d_in[1];
    const float* emb       = (const float*)d_in[2];
    const float* wx        = (const float*)d_in[3];
    const float* wh        = (const float*)d_in[4];
    const float* wo        = (const float*)d_in[5];
    float* out = (float*)d_out;

    init_kernel<<<48, 256>>>(h0);

    int cur = 0;
    for (int t = 0; t < T; t++) {
        dim3 gtp(NCHUNK, B);
        topk_partial_kernel<<<gtp, 256>>>(logprobs0, t == 0 ? 1 : 0);
        reduce_select_kernel<<<1, 320>>>(t, cur);
        if (t < T - 1) {
            rnn_partial_kernel<<<128, 256>>>(emb, wx, wh, cur);
            rnn_combine_kernel<<<40, 256>>>(cur ^ 1);
            logits_kernel<<<LOG_BLOCKS, LOG_THREADS>>>(wo, cur ^ 1);
        }
        cur ^= 1;
    }
    finalize_kernel<<<2, 256>>>(out, cur);
}

// round 3
// speedup vs baseline: 3.1213x; 1.2040x over previous
#include <cuda_runtime.h>
#include <math.h>

#define B   10
#define V   50257
#define D   1024
#define T   20
#define NCHUNK 13
#define CHUNK  4096   // 13*4096 = 53248 >= V

#define RNN_KS 32     // k-slices of 32

// ------------------------- device scratch (no allocs allowed) -------------
__device__ float g_logits[B * V];
__device__ float g_pm[B * NCHUNK];
__device__ float g_ps[B * NCHUNK];
__device__ float g_pv[B * NCHUNK * B];
__device__ int   g_pi[B * NCHUNK * B];
__device__ int   g_tokens[B];
__device__ int   g_q[B];
__device__ int   g_seq[2][T * B];
__device__ float g_lp[2][T * B];
__device__ float g_bsum[2][B];
__device__ float g_h[2][B * D];
__device__ float g_rpart[RNN_KS][B * D];

// --------------------------- helpers ---------------------------------------
__device__ __forceinline__ unsigned long long fma2(unsigned long long a,
                                                   unsigned long long b,
                                                   unsigned long long c) {
    unsigned long long d;
    asm("fma.rn.f32x2 %0, %1, %2, %3;" : "=l"(d) : "l"(a), "l"(b), "l"(c));
    return d;
}
__device__ __forceinline__ unsigned long long pack2(float w) {
    unsigned int wu = __float_as_uint(w);
    unsigned long long r;
    asm("mov.b64 %0, {%1, %1};" : "=l"(r) : "r"(wu));
    return r;
}
__device__ __forceinline__ void unpack2(unsigned long long a, float& lo, float& hi) {
    unsigned int l, h;
    asm("mov.b64 {%0, %1}, %2;" : "=r"(l), "=r"(h) : "l"(a));
    lo = __uint_as_float(l); hi = __uint_as_float(h);
}

// --------------------------- init ------------------------------------------
__global__ void init_kernel(const float* __restrict__ h0) {
    int i = blockIdx.x * 256 + threadIdx.x;
    if (i < B * D) g_h[0][i] = h0[i];
    if (i < T * B) { g_seq[0][i] = 0; g_seq[1][i] = 0; g_lp[0][i] = 0.f; g_lp[1][i] = 0.f; }
    if (i < B)     { g_bsum[0][i] = 0.f; g_bsum[1][i] = 0.f; }
}

// --------------------------- top-k partial ----------------------------------
// grid (NCHUNK, B), 256 threads. Per-thread sorted top-10 + online logsumexp,
// then block tournament reduce (per-thread lists, pop winner's head).
__global__ void topk_partial_kernel(const float* __restrict__ src, int use_input) {
    const int beam = blockIdx.y, chunk = blockIdx.x, tid = threadIdx.x;
    const float* row = (use_input ? src : (const float*)g_logits) + beam * V;
    const int c0 = chunk * CHUNK;
    const int c1 = min(c0 + CHUNK, V);

    float m = -1e30f, s = 0.f;
    float tv[10]; int ti[10];
#pragma unroll
    for (int p = 0; p < 10; p++) { tv[p] = -1e30f; ti[p] = 0x7FFFFFFF; }

    for (int c = c0 + tid; c < c1; c += 256) {
        float x = row[c];
        if (x > m) { s = s * __expf(m - x) + 1.f; m = x; }
        else       { s += __expf(x - m); }
        float v = (c == V - 1) ? x - 1000.f : x;    // UNK suppression (top-k only)
        if (v > tv[9] || (v == tv[9] && c < ti[9])) {
            tv[9] = v; ti[9] = c;
#pragma unroll
            for (int p = 9; p > 0; p--) {
                bool sw = (tv[p] > tv[p-1]) || (tv[p] == tv[p-1] && ti[p] < ti[p-1]);
                if (sw) {
                    float tf = tv[p]; tv[p] = tv[p-1]; tv[p-1] = tf;
                    int   tt = ti[p]; ti[p] = ti[p-1]; ti[p-1] = tt;
                }
            }
        }
    }

    // block logsumexp reduce
    __shared__ float sm[256], ss[256];
    sm[tid] = m; ss[tid] = s; __syncthreads();
    for (int off = 128; off > 0; off >>= 1) {
        if (tid < off) {
            float m1 = sm[tid], s1 = ss[tid], m2 = sm[tid + off], s2 = ss[tid + off];
            float mm = fmaxf(m1, m2);
            sm[tid] = mm;
            ss[tid] = s1 * __expf(m1 - mm) + s2 * __expf(m2 - mm);
        }
        __syncthreads();
    }
    if (tid == 0) { g_pm[beam * NCHUNK + chunk] = sm[0]; g_ps[beam * NCHUNK + chunk] = ss[0]; }

    // block top-10 tournament over 256 sorted per-thread lists
    __shared__ float rv[256]; __shared__ int rc[256]; __shared__ int rt[256];
    for (int r = 0; r < 10; r++) {
        rv[tid] = tv[0]; rc[tid] = ti[0]; rt[tid] = tid;
        __syncthreads();
        for (int off = 128; off > 0; off >>= 1) {
            if (tid < off) {
                bool take = (rv[tid+off] > rv[tid]) ||
                            (rv[tid+off] == rv[tid] && rc[tid+off] < rc[tid]);
                if (take) { rv[tid] = rv[tid+off]; rc[tid] = rc[tid+off]; rt[tid] = rt[tid+off]; }
            }
            __syncthreads();
        }
        if (tid == 0) {
            int slot = (beam * NCHUNK + chunk) * 10 + r;
            g_pv[slot] = rv[0]; g_pi[slot] = rc[0];
        }
        int wint = rt[0];
        __syncthreads();
        if (tid == wint) {
#pragma unroll
            for (int p = 0; p < 9; p++) { tv[p] = tv[p+1]; ti[p] = ti[p+1]; }
            tv[9] = -1e30f; ti[9] = 0x7FFFFFFF;
        }
    }
}

// --------------------------- reduce + select --------------------------------
// 1 block x 320 threads. Warp w<10 merges beam w's 13 partial lists + lse via
// shuffles; then warp 0 does the global 100->10 selection; then bookkeeping.
__global__ void reduce_select_kernel(int t, int cur) {
    __shared__ float s_topv[100];
    __shared__ int   s_topi[100];
    __shared__ int   s_q[10], s_tok[10];
    __shared__ float s_loc[10], s_ns[10];
    const unsigned FULL = 0xffffffffu;
    int tid = threadIdx.x, w = tid >> 5, lane = tid & 31;
    int nxt = cur ^ 1;

    if (w < 10) {
        int beam = w;
        // logsumexp across chunks
        float m = -1e30f, s = 0.f;
        if (lane < NCHUNK) { m = g_pm[beam * NCHUNK + lane]; s = g_ps[beam * NCHUNK + lane]; }
#pragma unroll
        for (int off = 16; off > 0; off >>= 1) {
            float m2 = __shfl_down_sync(FULL, m, off);
            float s2 = __shfl_down_sync(FULL, s, off);
            float mm = fmaxf(m, m2);
            s = s * __expf(m - mm) + s2 * __expf(m2 - mm);
            m = mm;
        }
        float mf = __shfl_sync(FULL, m, 0);
        float sf = __shfl_sync(FULL, s, 0);
        float lse = logf(sf) + mf;

        // lane l owns sorted partial list l (preloaded into registers)
        float lv[10]; int li[10];
        if (lane < NCHUNK) {
            int base = (beam * NCHUNK + lane) * 10;
#pragma unroll
            for (int p = 0; p < 10; p++) { lv[p] = g_pv[base + p]; li[p] = g_pi[base + p]; }
        } else {
#pragma unroll
            for (int p = 0; p < 10; p++) { lv[p] = -1e30f; li[p] = 0x7FFFFFFF; }
        }
        for (int r = 0; r < 10; r++) {
            float v = lv[0]; int c = li[0]; int l = lane;
#pragma unroll
            for (int off = 16; off > 0; off >>= 1) {
                float v2 = __shfl_down_sync(FULL, v, off);
                int   c2 = __shfl_down_sync(FULL, c, off);
                int   l2 = __shfl_down_sync(FULL, l, off);
                if (v2 > v || (v2 == v && c2 < c)) { v = v2; c = c2; l = l2; }
            }
            v = __shfl_sync(FULL, v, 0); c = __shfl_sync(FULL, c, 0); l = __shfl_sync(FULL, l, 0);
            if (lane == 0) { s_topv[beam * 10 + r] = v - lse; s_topi[beam * 10 + r] = c; }
            if (lane == l) {
#pragma unroll
                for (int p = 0; p < 9; p++) { lv[p] = lv[p+1]; li[p] = li[p+1]; }
                lv[9] = -1e30f; li[9] = 0x7FFFFFFF;
            }
        }
    }
    __syncthreads();

    if (w == 0) {
        float cv[4]; int cf[4];
#pragma unroll
        for (int j = 0; j < 4; j++) {
            int f = lane + 32 * j;
            if (f < 100) {
                int i = f / 10;
                float val = g_bsum[cur][i] + s_topv[f];
                if (t == 0 && i > 0) val = -1e10f;
                cv[j] = val; cf[j] = f;
            } else { cv[j] = -1e30f; cf[j] = 0x7FFFFFFF; }
        }
        for (int r = 0; r < 10; r++) {
            float bv = -1e30f; int bf = 0x7FFFFFFF;
#pragma unroll
            for (int j = 0; j < 4; j++)
                if (cv[j] > bv || (cv[j] == bv && cf[j] < bf)) { bv = cv[j]; bf = cf[j]; }
#pragma unroll
            for (int off = 16; off > 0; off >>= 1) {
                float v2 = __shfl_down_sync(FULL, bv, off);
                int   f2 = __shfl_down_sync(FULL, bf, off);
                if (v2 > bv || (v2 == bv && f2 < bf)) { bv = v2; bf = f2; }
            }
            bv = __shfl_sync(FULL, bv, 0); bf = __shfl_sync(FULL, bf, 0);
            if (lane == 0) {
                int qq = bf / 10;
                s_q[r] = qq; s_tok[r] = s_topi[bf]; s_loc[r] = s_topv[bf]; s_ns[r] = bv;
            }
#pragma unroll
            for (int j = 0; j < 4; j++) if (cf[j] == bf) cv[j] = -1e30f;
        }
    }
    __syncthreads();

    if (tid < 10) {
        g_tokens[tid] = s_tok[tid];
        g_q[tid]      = s_q[tid];
        g_bsum[nxt][tid] = (s_tok[tid] == 0) ? -1000.0f : s_ns[tid];
    }
    for (int i = tid; i < T * B; i += 320) {
        int b = i % 10, row = i / 10;
        int sb = s_q[b];
        int sv; float lv2;
        if (row == t) { sv = s_tok[b]; lv2 = s_loc[b]; }
        else          { sv = g_seq[cur][row * 10 + sb]; lv2 = g_lp[cur][row * 10 + sb]; }
        g_seq[nxt][i] = sv; g_lp[nxt][i] = lv2;
    }
}

// --------------------------- RNN (split-K partials) ------------------------
// grid 128 = 4 col-blocks(256 cols) x 32 k-slices(32 k), 256 threads.
// All 64 weight loads batched up-front: 256B/thread in flight (8MB chip).
__global__ __launch_bounds__(256) void rnn_partial_kernel(
        const float* __restrict__ emb,
        const float* __restrict__ wx,
        const float* __restrict__ wh, int cur) {
    __shared__ float se[32 * 12], shh[32 * 12];
    __shared__ int stok[10], sq[10];
    int bx = blockIdx.x;
    int cb = bx & 3, ks = bx >> 2;
    int tid = threadIdx.x;
    int k0 = ks * 32;
    int col = cb * 256 + tid;

    if (tid < 10) { stok[tid] = g_tokens[tid]; sq[tid] = g_q[tid]; }

    // batch all weight loads first (independent of shared staging)
    float wxv[32], whv[32];
#pragma unroll
    for (int kk = 0; kk < 32; kk++)
        wxv[kk] = __ldg(&wx[(size_t)(k0 + kk) * D + col]);
#pragma unroll
    for (int kk = 0; kk < 32; kk++)
        whv[kk] = __ldg(&wh[(size_t)(k0 + kk) * D + col]);

    __syncthreads();
    for (int i = tid; i < 320; i += 256) {
        int b = i >> 5, kk = i & 31;
        se[kk * 12 + b]  = emb[(size_t)stok[b] * D + k0 + kk];
        shh[kk * 12 + b] = g_h[cur][sq[b] * D + k0 + kk];
    }
    __syncthreads();

    float acc[10];
#pragma unroll
    for (int b = 0; b < 10; b++) acc[b] = 0.f;
#pragma unroll
    for (int kk = 0; kk < 32; kk++) {
#pragma unroll
        for (int b = 0; b < 10; b++)
            acc[b] += se[kk * 12 + b] * wxv[kk] + shh[kk * 12 + b] * whv[kk];
    }
#pragma unroll
    for (int b = 0; b < 10; b++) g_rpart[ks][b * D + col] = acc[b];
}

__global__ void rnn_combine_kernel(int nxt) {
    int i = blockIdx.x * 256 + threadIdx.x;
    if (i < B * D) {
        float v = 0.f;
#pragma unroll
        for (int ks = 0; ks < RNN_KS; ks++) v += g_rpart[ks][i];
        g_h[nxt][i] = tanhf(v);
    }
}

// --------------------------- logits = h @ wo (f32x2 packed) ----------------
// grid 148 x 352. 340 cols per block, one column per thread. K in chunks of
// 32 with all loads batched up front (6.4MB in flight chip-wide). Shared h
// fetched via 2x LDS.128 + 1x LDS.64 per k.
#define LOG_BLOCKS  148
#define LOG_TPB     352
#define LOG_COLS    340
#define LOG_KB      32
__global__ __launch_bounds__(LOG_TPB) void logits_kernel(
        const float* __restrict__ wo, int hbuf) {
    __shared__ unsigned long long hs2[D * 6];   // [k][beam-pair], 48KB
    float* hsf = (float*)hs2;
    const float* h = g_h[hbuf];
    for (int i = threadIdx.x; i < B * D; i += LOG_TPB) {
        int b = i >> 10, k = i & 1023;
        hsf[k * 12 + b] = h[i];
    }
    __syncthreads();

    int c = blockIdx.x * LOG_COLS + threadIdx.x;
    if (threadIdx.x >= LOG_COLS || c >= V) return;
    const float* wcol = wo + c;

    unsigned long long a0 = 0, a1 = 0, a2 = 0, a3 = 0, a4 = 0;
    for (int k0 = 0; k0 < D; k0 += LOG_KB) {
        float w[LOG_KB];
#pragma unroll
        for (int i = 0; i < LOG_KB; i++)
            w[i] = __ldg(wcol + (size_t)(k0 + i) * V);
#pragma unroll
        for (int i = 0; i < LOG_KB; i++) {
            unsigned long long w2 = pack2(w[i]);
            const ulonglong2* hp2 = (const ulonglong2*)&hs2[(k0 + i) * 6];
            ulonglong2 p01 = hp2[0];
            ulonglong2 p23 = hp2[1];
            unsigned long long p4 = hs2[(k0 + i) * 6 + 4];
            a0 = fma2(p01.x, w2, a0);
            a1 = fma2(p01.y, w2, a1);
            a2 = fma2(p23.x, w2, a2);
            a3 = fma2(p23.y, w2, a3);
            a4 = fma2(p4,    w2, a4);
        }
    }
    float lo, hi;
    unpack2(a0, lo, hi); g_logits[0 * V + c] = lo; g_logits[1 * V + c] = hi;
    unpack2(a1, lo, hi); g_logits[2 * V + c] = lo; g_logits[3 * V + c] = hi;
    unpack2(a2, lo, hi); g_logits[4 * V + c] = lo; g_logits[5 * V + c] = hi;
    unpack2(a3, lo, hi); g_logits[6 * V + c] = lo; g_logits[7 * V + c] = hi;
    unpack2(a4, lo, hi); g_logits[8 * V + c] = lo; g_logits[9 * V + c] = hi;
}

// --------------------------- finalize ---------------------------------------
__global__ void finalize_kernel(float* __restrict__ out, int cur) {
    int i = blockIdx.x * 256 + threadIdx.x;
    if (i < T * B)               out[i] = (float)g_seq[cur][i];
    else if (i < 2 * T * B)      out[i] = g_lp[cur][i - T * B];
    else if (i < 2 * T * B + B)  out[i] = g_bsum[cur][i - 2 * T * B];
}

// --------------------------- host driver ------------------------------------
extern "C" void kernel_launch(void* const* d_in, const int* in_sizes, int n_in,
                              void* d_out, int out_size) {
    const float* logprobs0 = (const float*)d_in[0];
    const float* h0        = (const float*)d_in[1];
    const float* emb       = (const float*)d_in[2];
    const float* wx        = (const float*)d_in[3];
    const float* wh        = (const float*)d_in[4];
    const float* wo        = (const float*)d_in[5];
    float* out = (float*)d_out;

    init_kernel<<<48, 256>>>(h0);

    int cur = 0;
    for (int t = 0; t < T; t++) {
        dim3 gtp(NCHUNK, B);
        topk_partial_kernel<<<gtp, 256>>>(logprobs0, t == 0 ? 1 : 0);
        reduce_select_kernel<<<1, 320>>>(t, cur);
        if (t < T - 1) {
            rnn_partial_kernel<<<128, 256>>>(emb, wx, wh, cur);
            rnn_combine_kernel<<<40, 256>>>(cur ^ 1);
            logits_kernel<<<LOG_BLOCKS, LOG_TPB>>>(wo, cur ^ 1);
        }
        cur ^= 1;
    }
    finalize_kernel<<<2, 256>>>(out, cur);
}